// round 3
// baseline (speedup 1.0000x reference)
#include <cuda_runtime.h>
#include <cstdint>
#include <cstddef>

// Problem constants
#define B_  256
#define T_  1024
#define I_  8
#define H_  256
#define L_  32          // steps per chunk
#define C_  32          // number of chunks (C_*L_ == T_)
#define BH  (B_*H_)
#define R_  16          // batch rows per scan CTA
#define NRG (B_/R_)     // 16 row groups -> 512 scan CTAs

// ---------------- device scratch (no allocations allowed) ----------------
__device__ float g_xw[(size_t)T_ * BH];      // input projections xw[t][b][h]
__device__ float g_At[H_ * H_];              // A = Wh^T  (h_new = h @ A)
__device__ float g_T1[H_ * H_];
__device__ float g_T2[H_ * H_];
__device__ float g_P32[H_ * H_];             // A^32
__device__ float g_Zend[(size_t)C_ * BH];    // chunk-final partials (zero-init scans)
__device__ float g_Hstart[(size_t)C_ * BH];  // true chunk start states

// ---------------- packed f32x2 helpers ----------------
__device__ __forceinline__ unsigned long long pack2(float v) {
    unsigned long long r;
    asm("mov.b64 %0, {%1, %1};" : "=l"(r) : "f"(v));
    return r;
}
__device__ __forceinline__ void fma2(unsigned long long& d,
                                     unsigned long long a,
                                     unsigned long long b) {
    asm("fma.rn.f32x2 %0, %1, %2, %0;" : "+l"(d) : "l"(a), "l"(b));
}

// ---------------- out[0] = broadcast h0 ----------------
__global__ void k_out0(float* __restrict__ out, const float* __restrict__ h0) {
    int idx = blockIdx.x * 256 + threadIdx.x;           // 65536 total
    out[idx] = h0[idx & (H_ - 1)];
}

// ---------------- xw[t] = x[:,t,:] @ Wx^T ----------------
__global__ void k_xw(const float* __restrict__ x, const float* __restrict__ Wx) {
    const int t   = blockIdx.x;       // 0..T-1
    const int tau = threadIdx.x;      // = output h index
    float wx[I_];
#pragma unroll
    for (int i = 0; i < I_; i++) wx[i] = Wx[tau * I_ + i];

    __shared__ float xs[32][I_];
    const int br = tau >> 3;          // 0..31
    const int ii = tau & 7;

    for (int b0 = 0; b0 < B_; b0 += 32) {
        xs[br][ii] = x[((size_t)(b0 + br) * T_ + t) * I_ + ii];
        __syncthreads();
#pragma unroll 4
        for (int bb = 0; bb < 32; bb++) {
            float s = 0.f;
#pragma unroll
            for (int i = 0; i < I_; i++) s += xs[bb][i] * wx[i];
            g_xw[((size_t)t * B_ + (b0 + bb)) * H_ + tau] = s;
        }
        __syncthreads();
    }
}

// ---------------- g_At = Wh^T ----------------
__global__ void k_transpose(const float* __restrict__ Wh) {
    int idx = blockIdx.x * 256 + threadIdx.x;   // 65536
    int h  = idx >> 8;
    int h2 = idx & 255;
    g_At[idx] = Wh[h2 * H_ + h];                // A[h][h'] = Wh[h'][h]
}

// ---------------- squaring chain for A^32 ----------------
__global__ void k_square(int step) {
    const float* src;
    float* dst;
    switch (step) {
        case 0: src = g_At; dst = g_T1;  break;   // A^2
        case 1: src = g_T1; dst = g_T2;  break;   // A^4
        case 2: src = g_T2; dst = g_T1;  break;   // A^8
        case 3: src = g_T1; dst = g_T2;  break;   // A^16
        default:src = g_T2; dst = g_P32; break;   // A^32
    }
    __shared__ float as[32][33], bs[32][33];
    const int tx = threadIdx.x & 31;
    const int ty = threadIdx.x >> 5;            // 0..7
    const int row0 = blockIdx.y * 32, col0 = blockIdx.x * 32;
    float acc[4] = {0.f, 0.f, 0.f, 0.f};
    for (int k0 = 0; k0 < H_; k0 += 32) {
#pragma unroll
        for (int e = 0; e < 4; e++) {
            int r = ty + e * 8;
            as[r][tx] = src[(size_t)(row0 + r) * H_ + k0 + tx];
            bs[r][tx] = src[(size_t)(k0 + r) * H_ + col0 + tx];
        }
        __syncthreads();
#pragma unroll
        for (int kk = 0; kk < 32; kk++) {
            float bv = bs[kk][tx];
#pragma unroll
            for (int e = 0; e < 4; e++) acc[e] += as[ty + e * 8][kk] * bv;
        }
        __syncthreads();
    }
#pragma unroll
    for (int e = 0; e < 4; e++)
        dst[(size_t)(row0 + ty + e * 8) * H_ + col0 + tx] = acc[e];
}

// ---------------- chunked scan ----------------
// R_=16 rows per CTA -> 512 CTAs, ~4 CTAs/SM (16 warps) for L2-latency hiding.
// PASS 0: zero-init scan, stores only Zend[c].
// PASS 1: scan from Hstart[c], writes out[t] for t in chunk.
template <int PASS>
__global__ void __launch_bounds__(256, 4) k_scan(float* __restrict__ out) {
    extern __shared__ float sm[];
    float* zb[2] = { sm, sm + R_ * H_ };

    const int c    = blockIdx.x & (C_ - 1);   // chunk
    const int rg   = blockIdx.x >> 5;         // row group 0..15
    const int r0   = rg * R_;
    const int tau  = threadIdx.x;
    const int rowg = tau >> 5;                // warp id 0..7 -> 2 rows each
    const int cg   = tau & 31;
    const int c0   = cg * 8;                  // 8 output columns

    // init z buffer: PASS0 -> xw of first step; PASS1 -> Hstart
    {
        const float* src = (PASS == 0)
            ? (g_xw + (size_t)(c * L_) * BH + (size_t)r0 * H_)
            : (g_Hstart + (size_t)c * BH + (size_t)r0 * H_);
        const unsigned long long* s = (const unsigned long long*)src;
        unsigned long long* d = (unsigned long long*)zb[0];
#pragma unroll
        for (int k = 0; k < 8; k++) d[tau + k * 256] = s[tau + k * 256];
    }
    __syncthreads();

    int p = 0;
    const int jstart = (PASS == 0) ? 2 : 1;

    for (int j = jstart; j <= L_; ++j) {
        const int t = c * L_ + j;             // global time step (1..T)
        unsigned long long acc[2][4];
#pragma unroll
        for (int i = 0; i < 2; i++) {
            const unsigned long long* xr = (const unsigned long long*)
                (g_xw + (size_t)(t - 1) * BH + (size_t)(r0 + rowg * 2 + i) * H_ + c0);
            acc[i][0] = xr[0]; acc[i][1] = xr[1];
            acc[i][2] = xr[2]; acc[i][3] = xr[3];
        }
        const float* zrow = zb[p] + rowg * 2 * H_;
#pragma unroll 8
        for (int h = 0; h < H_; ++h) {
            const ulonglong2* ar = (const ulonglong2*)(g_At + h * H_ + c0);
            ulonglong2 a01 = ar[0];
            ulonglong2 a23 = ar[1];
#pragma unroll
            for (int i = 0; i < 2; i++) {
                unsigned long long zz = pack2(zrow[i * H_ + h]);
                fma2(acc[i][0], zz, a01.x);
                fma2(acc[i][1], zz, a01.y);
                fma2(acc[i][2], zz, a23.x);
                fma2(acc[i][3], zz, a23.y);
            }
        }
#pragma unroll
        for (int i = 0; i < 2; i++) {
            unsigned long long* w =
                (unsigned long long*)(zb[p ^ 1] + (rowg * 2 + i) * H_ + c0);
            w[0] = acc[i][0]; w[1] = acc[i][1];
            w[2] = acc[i][2]; w[3] = acc[i][3];
            if (PASS == 1) {
                unsigned long long* o = (unsigned long long*)
                    (out + (size_t)t * BH + (size_t)(r0 + rowg * 2 + i) * H_ + c0);
                o[0] = acc[i][0]; o[1] = acc[i][1];
                o[2] = acc[i][2]; o[3] = acc[i][3];
            }
        }
        __syncthreads();
        p ^= 1;
    }

    if (PASS == 0) {
        const unsigned long long* s = (const unsigned long long*)zb[p];
        unsigned long long* d = (unsigned long long*)
            (g_Zend + (size_t)c * BH + (size_t)r0 * H_);
#pragma unroll
        for (int k = 0; k < 8; k++) d[tau + k * 256] = s[tau + k * 256];
    }
}

// ---------------- carry: Hstart[c+1] = Hstart[c] @ A^32 + Zend[c] ----------------
__global__ void __launch_bounds__(256, 1) k_carry(const float* __restrict__ h0) {
    __shared__ float hb[2][4 * H_];
    const int r0   = blockIdx.x * 4;          // 64 blocks x 4 rows
    const int tau  = threadIdx.x;
    const int rowg = tau >> 6;                // 0..3
    const int lg   = tau & 63;
    const int c0   = lg * 4;                  // 4 output cols per thread

    // Hstart[0] = broadcast h0
#pragma unroll
    for (int e = 0; e < 4; e++) {
        float v = h0[tau];
        hb[0][e * H_ + tau] = v;
        g_Hstart[(size_t)(r0 + e) * H_ + tau] = v;
    }
    __syncthreads();

    int p = 0;
    for (int c = 0; c < C_ - 1; c++) {
        unsigned long long acc[2];
        const unsigned long long* zs = (const unsigned long long*)
            (g_Zend + (size_t)c * BH + (size_t)(r0 + rowg) * H_ + c0);
        acc[0] = zs[0]; acc[1] = zs[1];
        const float* zr = hb[p] + rowg * H_;
#pragma unroll 4
        for (int h = 0; h < H_; h++) {
            ulonglong2 aa = *(const ulonglong2*)(g_P32 + h * H_ + c0);
            unsigned long long zz = pack2(zr[h]);
            fma2(acc[0], zz, aa.x);
            fma2(acc[1], zz, aa.y);
        }
        unsigned long long* w = (unsigned long long*)(hb[p ^ 1] + rowg * H_ + c0);
        w[0] = acc[0]; w[1] = acc[1];
        unsigned long long* g = (unsigned long long*)
            (g_Hstart + (size_t)(c + 1) * BH + (size_t)(r0 + rowg) * H_ + c0);
        g[0] = acc[0]; g[1] = acc[1];
        __syncthreads();
        p ^= 1;
    }
}

// ---------------- launch ----------------
extern "C" void kernel_launch(void* const* d_in, const int* in_sizes, int n_in,
                              void* d_out, int out_size) {
    (void)in_sizes; (void)n_in; (void)out_size;
    const float* x  = (const float*)d_in[0];
    const float* Wh = (const float*)d_in[1];
    const float* Wx = (const float*)d_in[2];
    const float* h0 = (const float*)d_in[3];
    float* out = (float*)d_out;

    const int smem = 2 * R_ * H_ * (int)sizeof(float);   // 32768 bytes
    cudaFuncSetAttribute(k_scan<0>, cudaFuncAttributeMaxDynamicSharedMemorySize, smem);
    cudaFuncSetAttribute(k_scan<1>, cudaFuncAttributeMaxDynamicSharedMemorySize, smem);

    // ncu (-s 5 -c 1) captures the 6th process launch; harness poison-memset is
    // launch 0, so my 0-based launch #4 is captured -> put k_scan<0> there.
    k_xw<<<T_, 256>>>(x, Wx);                   // 0
    k_transpose<<<256, 256>>>(Wh);              // 1
    k_out0<<<256, 256>>>(out, h0);              // 2
    dim3 g8(8, 8);
    k_square<<<g8, 256>>>(0);                   // 3  A^2
    k_scan<0><<<C_ * NRG, 256, smem>>>(out);    // 4  partials -> Zend (PROFILED)
    k_square<<<g8, 256>>>(1);                   // 5  A^4
    k_square<<<g8, 256>>>(2);                   // 6  A^8
    k_square<<<g8, 256>>>(3);                   // 7  A^16
    k_square<<<g8, 256>>>(4);                   // 8  A^32
    k_carry<<<B_ / 4, 256>>>(h0);               // 9  chunk start states
    k_scan<1><<<C_ * NRG, 256, smem>>>(out);    // 10 final scan -> out
}

// round 4
// speedup vs baseline: 2.1344x; 2.1344x over previous
#include <cuda_runtime.h>
#include <cstdint>
#include <cstddef>

// Problem constants
#define B_  256
#define T_  1024
#define I_  8
#define H_  256
#define L_  32          // steps per chunk
#define C_  32          // number of chunks (C_*L_ == T_)
#define BH  (B_*H_)
#define R_  32          // batch rows per scan CTA
#define NRG (B_/R_)     // 8 row groups -> 256 scan CTAs? no: 8*32=256? grid = C_*NRG = 256

// ---------------- device scratch (no allocations allowed) ----------------
__device__ float g_xw[(size_t)T_ * BH];      // input projections xw[t][b][h]
__device__ float g_At[H_ * H_];              // A = Wh^T  (h_new = h @ A)
__device__ float g_T1[H_ * H_];
__device__ float g_T2[H_ * H_];
__device__ float g_P32[H_ * H_];             // A^32
__device__ float g_Zend[(size_t)C_ * BH];    // chunk-final partials (zero-init scans)
__device__ float g_Hstart[(size_t)C_ * BH];  // true chunk start states

// ---------------- packed f32x2 helpers ----------------
__device__ __forceinline__ unsigned long long pack2(float v) {
    unsigned long long r;
    asm("mov.b64 %0, {%1, %1};" : "=l"(r) : "f"(v));
    return r;
}
__device__ __forceinline__ void fma2(unsigned long long& d,
                                     unsigned long long a,
                                     unsigned long long b) {
    asm("fma.rn.f32x2 %0, %1, %2, %0;" : "+l"(d) : "l"(a), "l"(b));
}

// ---------------- out[0] = broadcast h0 ----------------
__global__ void k_out0(float* __restrict__ out, const float* __restrict__ h0) {
    int idx = blockIdx.x * 256 + threadIdx.x;           // 65536 total
    out[idx] = h0[idx & (H_ - 1)];
}

// ---------------- xw[t] = x[:,t,:] @ Wx^T ----------------
__global__ void k_xw(const float* __restrict__ x, const float* __restrict__ Wx) {
    const int t   = blockIdx.x;       // 0..T-1
    const int tau = threadIdx.x;      // = output h index
    float wx[I_];
#pragma unroll
    for (int i = 0; i < I_; i++) wx[i] = Wx[tau * I_ + i];

    __shared__ float xs[32][I_];
    const int br = tau >> 3;          // 0..31
    const int ii = tau & 7;

    for (int b0 = 0; b0 < B_; b0 += 32) {
        xs[br][ii] = x[((size_t)(b0 + br) * T_ + t) * I_ + ii];
        __syncthreads();
#pragma unroll 4
        for (int bb = 0; bb < 32; bb++) {
            float s = 0.f;
#pragma unroll
            for (int i = 0; i < I_; i++) s += xs[bb][i] * wx[i];
            g_xw[((size_t)t * B_ + (b0 + bb)) * H_ + tau] = s;
        }
        __syncthreads();
    }
}

// ---------------- g_At = Wh^T ----------------
__global__ void k_transpose(const float* __restrict__ Wh) {
    int idx = blockIdx.x * 256 + threadIdx.x;   // 65536
    int h  = idx >> 8;
    int h2 = idx & 255;
    g_At[idx] = Wh[h2 * H_ + h];                // A[h][h'] = Wh[h'][h]
}

// ---------------- squaring chain for A^32 ----------------
__global__ void k_square(int step) {
    const float* src;
    float* dst;
    switch (step) {
        case 0: src = g_At; dst = g_T1;  break;   // A^2
        case 1: src = g_T1; dst = g_T2;  break;   // A^4
        case 2: src = g_T2; dst = g_T1;  break;   // A^8
        case 3: src = g_T1; dst = g_T2;  break;   // A^16
        default:src = g_T2; dst = g_P32; break;   // A^32
    }
    __shared__ float as[32][33], bs[32][33];
    const int tx = threadIdx.x & 31;
    const int ty = threadIdx.x >> 5;            // 0..7
    const int row0 = blockIdx.y * 32, col0 = blockIdx.x * 32;
    float acc[4] = {0.f, 0.f, 0.f, 0.f};
    for (int k0 = 0; k0 < H_; k0 += 32) {
#pragma unroll
        for (int e = 0; e < 4; e++) {
            int r = ty + e * 8;
            as[r][tx] = src[(size_t)(row0 + r) * H_ + k0 + tx];
            bs[r][tx] = src[(size_t)(k0 + r) * H_ + col0 + tx];
        }
        __syncthreads();
#pragma unroll
        for (int kk = 0; kk < 32; kk++) {
            float bv = bs[kk][tx];
#pragma unroll
            for (int e = 0; e < 4; e++) acc[e] += as[ty + e * 8][kk] * bv;
        }
        __syncthreads();
    }
#pragma unroll
    for (int e = 0; e < 4; e++)
        dst[(size_t)(row0 + ty + e * 8) * H_ + col0 + tx] = acc[e];
}

// ---------------- chunked scan ----------------
// R_=32 rows/CTA, 128 CTAs. COALESCED column map: lane l owns columns
// [4l, 4l+4) and [128+4l, 128+4l+4) -> every A/xw LDG.128 and z/out STS/STG.128
// is a 16-byte-stride warp access (4 wavefronts, no wasted sectors).
// PASS 0: zero-init scan, stores only Zend[c].
// PASS 1: scan from Hstart[c], writes out[t] for t in chunk.
template <int PASS>
__global__ void __launch_bounds__(256, 2) k_scan(float* __restrict__ out) {
    extern __shared__ float sm[];
    float* zb[2] = { sm, sm + R_ * H_ };

    const int c    = blockIdx.x & (C_ - 1);   // chunk
    const int rg   = blockIdx.x >> 5;         // row group 0..7
    const int r0   = rg * R_;
    const int tau  = threadIdx.x;
    const int w    = tau >> 5;                // warp id 0..7 -> 4 rows each
    const int l    = tau & 31;
    const int cA   = l * 4;                   // low 4 columns
    const int cB   = 128 + l * 4;             // high 4 columns

    // init z buffer: PASS0 -> xw of first step; PASS1 -> Hstart  (coalesced u64 copy)
    {
        const float* src = (PASS == 0)
            ? (g_xw + (size_t)(c * L_) * BH + (size_t)r0 * H_)
            : (g_Hstart + (size_t)c * BH + (size_t)r0 * H_);
        const unsigned long long* s = (const unsigned long long*)src;
        unsigned long long* d = (unsigned long long*)zb[0];
#pragma unroll
        for (int k = 0; k < 16; k++) d[tau + k * 256] = s[tau + k * 256];
    }
    __syncthreads();

    int p = 0;
    const int jstart = (PASS == 0) ? 2 : 1;

    for (int j = jstart; j <= L_; ++j) {
        const int t = c * L_ + j;             // global time step (1..T)
        unsigned long long acc[4][4];         // 4 rows x (2 u64 low + 2 u64 high)
#pragma unroll
        for (int i = 0; i < 4; i++) {
            const float* xr = g_xw + (size_t)(t - 1) * BH
                                   + (size_t)(r0 + w * 4 + i) * H_;
            ulonglong2 xlo = *(const ulonglong2*)(xr + cA);
            ulonglong2 xhi = *(const ulonglong2*)(xr + cB);
            acc[i][0] = xlo.x; acc[i][1] = xlo.y;
            acc[i][2] = xhi.x; acc[i][3] = xhi.y;
        }
        const float* zrow = zb[p] + w * 4 * H_;
#pragma unroll 8
        for (int h = 0; h < H_; ++h) {
            ulonglong2 a_lo = *(const ulonglong2*)(g_At + h * H_ + cA);
            ulonglong2 a_hi = *(const ulonglong2*)(g_At + h * H_ + cB);
#pragma unroll
            for (int i = 0; i < 4; i++) {
                unsigned long long zz = pack2(zrow[i * H_ + h]);
                fma2(acc[i][0], zz, a_lo.x);
                fma2(acc[i][1], zz, a_lo.y);
                fma2(acc[i][2], zz, a_hi.x);
                fma2(acc[i][3], zz, a_hi.y);
            }
        }
#pragma unroll
        for (int i = 0; i < 4; i++) {
            float* zw = zb[p ^ 1] + (w * 4 + i) * H_;
            *(ulonglong2*)(zw + cA) = make_ulonglong2(acc[i][0], acc[i][1]);
            *(ulonglong2*)(zw + cB) = make_ulonglong2(acc[i][2], acc[i][3]);
            if (PASS == 1) {
                float* o = out + (size_t)t * BH + (size_t)(r0 + w * 4 + i) * H_;
                *(ulonglong2*)(o + cA) = make_ulonglong2(acc[i][0], acc[i][1]);
                *(ulonglong2*)(o + cB) = make_ulonglong2(acc[i][2], acc[i][3]);
            }
        }
        __syncthreads();
        p ^= 1;
    }

    if (PASS == 0) {
        const unsigned long long* s = (const unsigned long long*)zb[p];
        unsigned long long* d = (unsigned long long*)
            (g_Zend + (size_t)c * BH + (size_t)r0 * H_);
#pragma unroll
        for (int k = 0; k < 16; k++) d[tau + k * 256] = s[tau + k * 256];
    }
}

// ---------------- carry: Hstart[c+1] = Hstart[c] @ A^32 + Zend[c] ----------------
__global__ void __launch_bounds__(256, 1) k_carry(const float* __restrict__ h0) {
    __shared__ float hb[2][4 * H_];
    const int r0   = blockIdx.x * 4;          // 64 blocks x 4 rows
    const int tau  = threadIdx.x;
    const int rowg = tau >> 6;                // 0..3
    const int lg   = tau & 63;
    const int c0   = lg * 4;                  // 4 output cols per thread (coalesced)

    // Hstart[0] = broadcast h0
#pragma unroll
    for (int e = 0; e < 4; e++) {
        float v = h0[tau];
        hb[0][e * H_ + tau] = v;
        g_Hstart[(size_t)(r0 + e) * H_ + tau] = v;
    }
    __syncthreads();

    int p = 0;
    for (int c = 0; c < C_ - 1; c++) {
        unsigned long long acc[2];
        const unsigned long long* zs = (const unsigned long long*)
            (g_Zend + (size_t)c * BH + (size_t)(r0 + rowg) * H_ + c0);
        acc[0] = zs[0]; acc[1] = zs[1];
        const float* zr = hb[p] + rowg * H_;
#pragma unroll 4
        for (int h = 0; h < H_; h++) {
            ulonglong2 aa = *(const ulonglong2*)(g_P32 + h * H_ + c0);
            unsigned long long zz = pack2(zr[h]);
            fma2(acc[0], zz, aa.x);
            fma2(acc[1], zz, aa.y);
        }
        unsigned long long* w = (unsigned long long*)(hb[p ^ 1] + rowg * H_ + c0);
        w[0] = acc[0]; w[1] = acc[1];
        unsigned long long* g = (unsigned long long*)
            (g_Hstart + (size_t)(c + 1) * BH + (size_t)(r0 + rowg) * H_ + c0);
        g[0] = acc[0]; g[1] = acc[1];
        __syncthreads();
        p ^= 1;
    }
}

// ---------------- launch ----------------
extern "C" void kernel_launch(void* const* d_in, const int* in_sizes, int n_in,
                              void* d_out, int out_size) {
    (void)in_sizes; (void)n_in; (void)out_size;
    const float* x  = (const float*)d_in[0];
    const float* Wh = (const float*)d_in[1];
    const float* Wx = (const float*)d_in[2];
    const float* h0 = (const float*)d_in[3];
    float* out = (float*)d_out;

    const int smem = 2 * R_ * H_ * (int)sizeof(float);   // 65536 bytes
    cudaFuncSetAttribute(k_scan<0>, cudaFuncAttributeMaxDynamicSharedMemorySize, smem);
    cudaFuncSetAttribute(k_scan<1>, cudaFuncAttributeMaxDynamicSharedMemorySize, smem);

    // Empirically, ncu captures MY 0-based launch index 3 (2 harness launches
    // precede mine, -s 5). Put k_scan<0> there.
    k_xw<<<T_, 256>>>(x, Wx);                          // 0
    k_transpose<<<256, 256>>>(Wh);                     // 1
    k_out0<<<256, 256>>>(out, h0);                     // 2
    k_scan<0><<<C_ * NRG, 256, smem>>>(out);           // 3  partials -> Zend (PROFILED)
    dim3 g8(8, 8);
    k_square<<<g8, 256>>>(0);                          // 4  A^2
    k_square<<<g8, 256>>>(1);                          // 5  A^4
    k_square<<<g8, 256>>>(2);                          // 6  A^8
    k_square<<<g8, 256>>>(3);                          // 7  A^16
    k_square<<<g8, 256>>>(4);                          // 8  A^32
    k_carry<<<B_ / 4, 256>>>(h0);                      // 9  chunk start states
    k_scan<1><<<C_ * NRG, 256, smem>>>(out);           // 10 final scan -> out
}

// round 5
// speedup vs baseline: 2.2921x; 1.0739x over previous
#include <cuda_runtime.h>
#include <cstdint>
#include <cstddef>

// Problem constants
#define B_  256
#define T_  1024
#define I_  8
#define H_  256
#define L_  32          // steps per chunk
#define C_  32          // number of chunks (C_*L_ == T_)
#define BH  (B_*H_)
#define R_  64          // batch rows per scan CTA
#define NRG (B_/R_)     // 4 row groups -> 128 scan CTAs

// ---------------- device scratch (no allocations allowed) ----------------
__device__ float g_xw[(size_t)T_ * BH];      // input projections xw[t][b][h]
__device__ float g_At[H_ * H_];              // A = Wh^T  (h_new = h @ A)
__device__ float g_T1[H_ * H_];
__device__ float g_T2[H_ * H_];
__device__ float g_P32[H_ * H_];             // A^32
__device__ float g_Zend[(size_t)C_ * BH];    // chunk-final partials (zero-init scans)
__device__ float g_Hstart[(size_t)C_ * BH];  // true chunk start states

// ---------------- packed f32x2 helpers ----------------
__device__ __forceinline__ unsigned long long pack2(float v) {
    unsigned long long r;
    asm("mov.b64 %0, {%1, %1};" : "=l"(r) : "f"(v));
    return r;
}
__device__ __forceinline__ void fma2(unsigned long long& d,
                                     unsigned long long a,
                                     unsigned long long b) {
    asm("fma.rn.f32x2 %0, %1, %2, %0;" : "+l"(d) : "l"(a), "l"(b));
}

// ---------------- out[0] = broadcast h0 ----------------
__global__ void k_out0(float* __restrict__ out, const float* __restrict__ h0) {
    int idx = blockIdx.x * 256 + threadIdx.x;           // 65536 total
    out[idx] = h0[idx & (H_ - 1)];
}

// ---------------- xw[t] = x[:,t,:] @ Wx^T ----------------
__global__ void k_xw(const float* __restrict__ x, const float* __restrict__ Wx) {
    const int t   = blockIdx.x;       // 0..T-1
    const int tau = threadIdx.x;      // = output h index
    float wx[I_];
#pragma unroll
    for (int i = 0; i < I_; i++) wx[i] = Wx[tau * I_ + i];

    __shared__ float xs[32][I_];
    const int br = tau >> 3;          // 0..31
    const int ii = tau & 7;

    for (int b0 = 0; b0 < B_; b0 += 32) {
        xs[br][ii] = x[((size_t)(b0 + br) * T_ + t) * I_ + ii];
        __syncthreads();
#pragma unroll 4
        for (int bb = 0; bb < 32; bb++) {
            float s = 0.f;
#pragma unroll
            for (int i = 0; i < I_; i++) s += xs[bb][i] * wx[i];
            g_xw[((size_t)t * B_ + (b0 + bb)) * H_ + tau] = s;
        }
        __syncthreads();
    }
}

// ---------------- g_At = Wh^T ----------------
__global__ void k_transpose(const float* __restrict__ Wh) {
    int idx = blockIdx.x * 256 + threadIdx.x;   // 65536
    int h  = idx >> 8;
    int h2 = idx & 255;
    g_At[idx] = Wh[h2 * H_ + h];                // A[h][h'] = Wh[h'][h]
}

// ---------------- squaring chain for A^32 ----------------
__global__ void k_square(int step) {
    const float* src;
    float* dst;
    switch (step) {
        case 0: src = g_At; dst = g_T1;  break;   // A^2
        case 1: src = g_T1; dst = g_T2;  break;   // A^4
        case 2: src = g_T2; dst = g_T1;  break;   // A^8
        case 3: src = g_T1; dst = g_T2;  break;   // A^16
        default:src = g_T2; dst = g_P32; break;   // A^32
    }
    __shared__ float as[32][33], bs[32][33];
    const int tx = threadIdx.x & 31;
    const int ty = threadIdx.x >> 5;            // 0..7
    const int row0 = blockIdx.y * 32, col0 = blockIdx.x * 32;
    float acc[4] = {0.f, 0.f, 0.f, 0.f};
    for (int k0 = 0; k0 < H_; k0 += 32) {
#pragma unroll
        for (int e = 0; e < 4; e++) {
            int r = ty + e * 8;
            as[r][tx] = src[(size_t)(row0 + r) * H_ + k0 + tx];
            bs[r][tx] = src[(size_t)(k0 + r) * H_ + col0 + tx];
        }
        __syncthreads();
#pragma unroll
        for (int kk = 0; kk < 32; kk++) {
            float bv = bs[kk][tx];
#pragma unroll
            for (int e = 0; e < 4; e++) acc[e] += as[ty + e * 8][kk] * bv;
        }
        __syncthreads();
    }
#pragma unroll
    for (int e = 0; e < 4; e++)
        dst[(size_t)(row0 + ty + e * 8) * H_ + col0 + tx] = acc[e];
}

// ---------------- chunked scan ----------------
// R_=64 rows/CTA, 128 CTAs, 1 CTA/SM. Each warp owns 8 rows x 8 cols
// (cols {4l..4l+3, 128+4l..128+4l+3} -> all LDG/STS 16B-stride coalesced).
// A is read once per warp per step (amortized over 8 rows); z is read via
// broadcast LDS.128 (4 h-values per transaction).
// PASS 0: zero-init scan, stores only Zend[c].
// PASS 1: scan from Hstart[c], writes out[t] for t in chunk.
template <int PASS>
__global__ void __launch_bounds__(256, 1) k_scan(float* __restrict__ out) {
    extern __shared__ float sm[];
    float* zb[2] = { sm, sm + R_ * H_ };

    const int c    = blockIdx.x & (C_ - 1);   // chunk
    const int rg   = blockIdx.x >> 5;         // row group 0..3
    const int r0   = rg * R_;
    const int tau  = threadIdx.x;
    const int w    = tau >> 5;                // warp id 0..7 -> 8 rows each
    const int l    = tau & 31;
    const int cA   = l * 4;                   // low 4 columns
    const int cB   = 128 + l * 4;             // high 4 columns

    // init z buffer: PASS0 -> xw of first step; PASS1 -> Hstart (coalesced u64 copy)
    {
        const float* src = (PASS == 0)
            ? (g_xw + (size_t)(c * L_) * BH + (size_t)r0 * H_)
            : (g_Hstart + (size_t)c * BH + (size_t)r0 * H_);
        const unsigned long long* s = (const unsigned long long*)src;
        unsigned long long* d = (unsigned long long*)zb[0];
#pragma unroll
        for (int k = 0; k < 32; k++) d[tau + k * 256] = s[tau + k * 256];
    }
    __syncthreads();

    int p = 0;
    const int jstart = (PASS == 0) ? 2 : 1;

    for (int j = jstart; j <= L_; ++j) {
        const int t = c * L_ + j;             // global time step (1..T)
        unsigned long long acc[8][4];         // 8 rows x (2 u64 low + 2 u64 high)
#pragma unroll
        for (int i = 0; i < 8; i++) {
            const float* xr = g_xw + (size_t)(t - 1) * BH
                                   + (size_t)(r0 + w * 8 + i) * H_;
            ulonglong2 xlo = *(const ulonglong2*)(xr + cA);
            ulonglong2 xhi = *(const ulonglong2*)(xr + cB);
            acc[i][0] = xlo.x; acc[i][1] = xlo.y;
            acc[i][2] = xhi.x; acc[i][3] = xhi.y;
        }
        const float* zrow = zb[p] + w * 8 * H_;
#pragma unroll 2
        for (int hg = 0; hg < H_ / 4; ++hg) {
            float4 z4[8];
#pragma unroll
            for (int i = 0; i < 8; i++)
                z4[i] = *(const float4*)(zrow + i * H_ + hg * 4);
#pragma unroll
            for (int hh = 0; hh < 4; hh++) {
                const float* arow = g_At + (hg * 4 + hh) * H_;
                ulonglong2 a_lo = *(const ulonglong2*)(arow + cA);
                ulonglong2 a_hi = *(const ulonglong2*)(arow + cB);
#pragma unroll
                for (int i = 0; i < 8; i++) {
                    float zv = (hh == 0) ? z4[i].x
                             : (hh == 1) ? z4[i].y
                             : (hh == 2) ? z4[i].z : z4[i].w;
                    unsigned long long zz = pack2(zv);
                    fma2(acc[i][0], zz, a_lo.x);
                    fma2(acc[i][1], zz, a_lo.y);
                    fma2(acc[i][2], zz, a_hi.x);
                    fma2(acc[i][3], zz, a_hi.y);
                }
            }
        }
#pragma unroll
        for (int i = 0; i < 8; i++) {
            float* zw = zb[p ^ 1] + (w * 8 + i) * H_;
            *(ulonglong2*)(zw + cA) = make_ulonglong2(acc[i][0], acc[i][1]);
            *(ulonglong2*)(zw + cB) = make_ulonglong2(acc[i][2], acc[i][3]);
            if (PASS == 1) {
                float* o = out + (size_t)t * BH + (size_t)(r0 + w * 8 + i) * H_;
                *(ulonglong2*)(o + cA) = make_ulonglong2(acc[i][0], acc[i][1]);
                *(ulonglong2*)(o + cB) = make_ulonglong2(acc[i][2], acc[i][3]);
            }
        }
        __syncthreads();
        p ^= 1;
    }

    if (PASS == 0) {
        const unsigned long long* s = (const unsigned long long*)zb[p];
        unsigned long long* d = (unsigned long long*)
            (g_Zend + (size_t)c * BH + (size_t)r0 * H_);
#pragma unroll
        for (int k = 0; k < 32; k++) d[tau + k * 256] = s[tau + k * 256];
    }
}

// ---------------- carry: Hstart[c+1] = Hstart[c] @ A^32 + Zend[c] ----------------
__global__ void __launch_bounds__(256, 1) k_carry(const float* __restrict__ h0) {
    __shared__ float hb[2][4 * H_];
    const int r0   = blockIdx.x * 4;          // 64 blocks x 4 rows
    const int tau  = threadIdx.x;
    const int rowg = tau >> 6;                // 0..3
    const int lg   = tau & 63;
    const int c0   = lg * 4;                  // 4 output cols per thread (coalesced)

    // Hstart[0] = broadcast h0
#pragma unroll
    for (int e = 0; e < 4; e++) {
        float v = h0[tau];
        hb[0][e * H_ + tau] = v;
        g_Hstart[(size_t)(r0 + e) * H_ + tau] = v;
    }
    __syncthreads();

    int p = 0;
    for (int c = 0; c < C_ - 1; c++) {
        unsigned long long acc[2];
        const unsigned long long* zs = (const unsigned long long*)
            (g_Zend + (size_t)c * BH + (size_t)(r0 + rowg) * H_ + c0);
        acc[0] = zs[0]; acc[1] = zs[1];
        const float* zr = hb[p] + rowg * H_;
#pragma unroll 4
        for (int h = 0; h < H_; h++) {
            ulonglong2 aa = *(const ulonglong2*)(g_P32 + h * H_ + c0);
            unsigned long long zz = pack2(zr[h]);
            fma2(acc[0], zz, aa.x);
            fma2(acc[1], zz, aa.y);
        }
        unsigned long long* w = (unsigned long long*)(hb[p ^ 1] + rowg * H_ + c0);
        w[0] = acc[0]; w[1] = acc[1];
        unsigned long long* g = (unsigned long long*)
            (g_Hstart + (size_t)(c + 1) * BH + (size_t)(r0 + rowg) * H_ + c0);
        g[0] = acc[0]; g[1] = acc[1];
        __syncthreads();
        p ^= 1;
    }
}

// ---------------- launch ----------------
extern "C" void kernel_launch(void* const* d_in, const int* in_sizes, int n_in,
                              void* d_out, int out_size) {
    (void)in_sizes; (void)n_in; (void)out_size;
    const float* x  = (const float*)d_in[0];
    const float* Wh = (const float*)d_in[1];
    const float* Wx = (const float*)d_in[2];
    const float* h0 = (const float*)d_in[3];
    float* out = (float*)d_out;

    const int smem = 2 * R_ * H_ * (int)sizeof(float);   // 131072 bytes
    cudaFuncSetAttribute(k_scan<0>, cudaFuncAttributeMaxDynamicSharedMemorySize, smem);
    cudaFuncSetAttribute(k_scan<1>, cudaFuncAttributeMaxDynamicSharedMemorySize, smem);

    // ncu captures MY 0-based launch index 3 -> keep k_scan<0> there.
    k_xw<<<T_, 256>>>(x, Wx);                          // 0
    k_transpose<<<256, 256>>>(Wh);                     // 1
    k_out0<<<256, 256>>>(out, h0);                     // 2
    k_scan<0><<<C_ * NRG, 256, smem>>>(out);           // 3  partials -> Zend (PROFILED)
    dim3 g8(8, 8);
    k_square<<<g8, 256>>>(0);                          // 4  A^2
    k_square<<<g8, 256>>>(1);                          // 5  A^4
    k_square<<<g8, 256>>>(2);                          // 6  A^8
    k_square<<<g8, 256>>>(3);                          // 7  A^16
    k_square<<<g8, 256>>>(4);                          // 8  A^32
    k_carry<<<B_ / 4, 256>>>(h0);                      // 9  chunk start states
    k_scan<1><<<C_ * NRG, 256, smem>>>(out);           // 10 final scan -> out
}